// round 6
// baseline (speedup 1.0000x reference)
#include <cuda_runtime.h>
#include <math.h>

// Problem constants
#define CC    128
#define HWSZ  262144      // 512*512
#define BK    512         // B*K
#define NNEG  7
#define PP    4096
#define TAUI  (1.0f/0.07f)

// GEMM tiling
#define QT     32         // queries per block tile
#define PTILE  256        // protos per block
#define PCHUNK 128        // protos staged in smem at once
#define PSTR   132        // padded k-major stride for p tile
#define NPT    (PP/PTILE) // 16 proto tiles / 16 blocks per q-column

// Scratch (device globals — no allocation allowed; zero-init, self-resetting)
__device__ float        g_qn[BK*CC];     // normalized query vectors
__device__ float        g_pmax[BK*NPT];  // per (query, ptile) max similarity
__device__ float        g_partial[16];   // per q-column loss sums
__device__ unsigned int g_colcnt[16];    // blocks finished per q-column
__device__ unsigned int g_done;          // columns finished

// ---- packed fp32x2 helpers (sm_100+) --------------------------------------
__device__ __forceinline__ void ffma2(unsigned long long& acc,
                                      unsigned long long a, unsigned long long b) {
    asm("fma.rn.f32x2 %0, %1, %2, %0;" : "+l"(acc) : "l"(a), "l"(b));
}
__device__ __forceinline__ unsigned long long dup2(float x) {
    unsigned long long r;
    asm("mov.b64 %0, {%1, %1};" : "=l"(r) : "f"(x));
    return r;
}
__device__ __forceinline__ float2 unpack2(unsigned long long v) {
    float2 r;
    asm("mov.b64 {%0, %1}, %2;" : "=f"(r.x), "=f"(r.y) : "l"(v));
    return r;
}

// ---------------------------------------------------------------------------
// Single fused kernel, no spinning.  grid=(16,16), block=256
//   Phase 1 (all blocks): gather+normalize 32 queries, stage proto chunks
//     (norms during staging), 8q x 2p FFMA2 microtile, publish g_pmax slice.
//   Epilogue: last block per q-column computes that column's CE losses;
//     last column-finisher sums partials and writes out. Nobody waits.
// ---------------------------------------------------------------------------
__global__ void __launch_bounds__(256, 2)
k_fused(const float* __restrict__ pool,
        const float* __restrict__ qf,
        const int*   __restrict__ qidx,
        const float* __restrict__ neg,
        float* __restrict__ out) {
    extern __shared__ float sm[];
    float* q_t = sm;            // [128][QT]   k-major
    float* p_t = sm + CC * QT;  // [128][PSTR] k-major, padded
    __shared__ float psum[2 * PCHUNK];      // proto half sums of squares
    __shared__ float qpart[8 * QT];         // gather partial sums [seg][q]
    __shared__ unsigned int s_old;
    __shared__ float s_loss[8];

    int t     = threadIdx.x;
    int qbase = blockIdx.x * QT;
    int pbase = blockIdx.y * PTILE;

    // ---- issue the query gather loads first (16 independent LDG, MLP=16) ----
    int gq = t & 31, seg = t >> 5;                 // q within tile, c-segment
    int gidx = qidx[qbase + gq];
    int gb   = (qbase + gq) >> 6;
    const float* gsrc = qf + ((size_t)(gb * CC + seg * 16)) * HWSZ + (size_t)gidx;
    float gv[16];
    #pragma unroll
    for (int i = 0; i < 16; i++) gv[i] = gsrc[(size_t)i * HWSZ];

    // ---- stage proto chunk 0 (transposed) + per-half sumsq ----
    int sp = t & 127, half = t >> 7;
    {
        const float* src = pool + (size_t)(pbase + sp) * CC + half * 64;
        float ssp = 0.0f;
        #pragma unroll
        for (int i = 0; i < 16; i++) {
            float4 v = *(const float4*)(src + i * 4);
            ssp += v.x * v.x + v.y * v.y + v.z * v.z + v.w * v.w;
            int k0 = half * 64 + i * 4;
            p_t[(k0 + 0) * PSTR + sp] = v.x;
            p_t[(k0 + 1) * PSTR + sp] = v.y;
            p_t[(k0 + 2) * PSTR + sp] = v.z;
            p_t[(k0 + 3) * PSTR + sp] = v.w;
        }
        psum[half * PCHUNK + sp] = ssp;
    }

    // ---- finish query gather: partial sumsq -> reduce -> normalized store ----
    {
        float ss = 0.0f;
        #pragma unroll
        for (int i = 0; i < 16; i++) ss += gv[i] * gv[i];
        qpart[seg * QT + gq] = ss;
    }
    __syncthreads();
    {
        float tot = 0.0f;
        #pragma unroll
        for (int s = 0; s < 8; s++) tot += qpart[s * QT + gq];
        float inv = 1.0f / fmaxf(sqrtf(tot), 1e-12f);
        #pragma unroll
        for (int i = 0; i < 16; i++) {
            float nv = gv[i] * inv;
            q_t[(seg * 16 + i) * QT + gq] = nv;   // lanes vary q: no conflicts
            if (blockIdx.y == 0) g_qn[(qbase + gq) * CC + seg * 16 + i] = nv;
        }
    }

    int qrow = t >> 6;   // 0..3  -> queries 8*qrow .. +7
    int pcol = t & 63;   // 0..63 -> protos  2*pcol, 2*pcol+1 (within chunk)

    float bv[8];
    #pragma unroll
    for (int i = 0; i < 8; i++) bv[i] = -3e38f;

    #pragma unroll
    for (int c = 0; c < PTILE / PCHUNK; c++) {
        if (c > 0) {
            __syncthreads();   // previous chunk fully consumed
            const float* src = pool + (size_t)(pbase + c * PCHUNK + sp) * CC + half * 64;
            float ssp = 0.0f;
            #pragma unroll
            for (int i = 0; i < 16; i++) {
                float4 v = *(const float4*)(src + i * 4);
                ssp += v.x * v.x + v.y * v.y + v.z * v.z + v.w * v.w;
                int k0 = half * 64 + i * 4;
                p_t[(k0 + 0) * PSTR + sp] = v.x;
                p_t[(k0 + 1) * PSTR + sp] = v.y;
                p_t[(k0 + 2) * PSTR + sp] = v.z;
                p_t[(k0 + 3) * PSTR + sp] = v.w;
            }
            psum[half * PCHUNK + sp] = ssp;
        }
        __syncthreads();

        unsigned long long acc[4][2];
        #pragma unroll
        for (int i = 0; i < 4; i++) { acc[i][0] = 0ull; acc[i][1] = 0ull; }

        const float* qp = q_t + 8 * qrow;
        const float* pp = p_t + 2 * pcol;
        #pragma unroll 8
        for (int k = 0; k < CC; k++) {
            ulonglong2 qa = *(const ulonglong2*)(qp + k * QT);      // broadcast
            ulonglong2 qb = *(const ulonglong2*)(qp + k * QT + 4);  // broadcast
            float2 pv = *(const float2*)(pp + k * PSTR);
            unsigned long long d0 = dup2(pv.x);
            unsigned long long d1 = dup2(pv.y);
            ffma2(acc[0][0], qa.x, d0); ffma2(acc[0][1], qa.x, d1);
            ffma2(acc[1][0], qa.y, d0); ffma2(acc[1][1], qa.y, d1);
            ffma2(acc[2][0], qb.x, d0); ffma2(acc[2][1], qb.x, d1);
            ffma2(acc[3][0], qb.y, d0); ffma2(acc[3][1], qb.y, d1);
        }

        // proto reciprocal norms from staged sums of squares
        float r0 = 1.0f / fmaxf(sqrtf(psum[2*pcol]   + psum[PCHUNK + 2*pcol]),   1e-12f);
        float r1 = 1.0f / fmaxf(sqrtf(psum[2*pcol+1] + psum[PCHUNK + 2*pcol+1]), 1e-12f);
        #pragma unroll
        for (int i = 0; i < 4; i++) {
            float2 a0 = unpack2(acc[i][0]);
            float2 a1 = unpack2(acc[i][1]);
            bv[2*i]   = fmaxf(bv[2*i],   fmaxf(a0.x * r0, a1.x * r1));
            bv[2*i+1] = fmaxf(bv[2*i+1], fmaxf(a0.y * r0, a1.y * r1));
        }
    }

    // max across the 32 lanes of each warp (warp shares qrow)
    #pragma unroll
    for (int o = 16; o; o >>= 1)
        #pragma unroll
        for (int i = 0; i < 8; i++)
            bv[i] = fmaxf(bv[i], __shfl_down_sync(0xffffffffu, bv[i], o));

    // combine the two warps sharing each qrow via smem, publish g_pmax
    __syncthreads();
    int w = t >> 5;
    if ((t & 31) == 0) {
        #pragma unroll
        for (int i = 0; i < 8; i++) q_t[w * 8 + i] = bv[i];
    }
    __syncthreads();
    if (t < 32) {
        int r = t >> 3, qi = t & 7;
        float m = fmaxf(q_t[(2*r) * 8 + qi], q_t[(2*r+1) * 8 + qi]);
        g_pmax[(qbase + 8*r + qi) * NPT + blockIdx.y] = m;
    }

    // ---- arrive on the q-column counter; 15/16 blocks exit (no waiting) ----
    __syncthreads();
    if (t == 0) {
        __threadfence();
        s_old = atomicAdd(&g_colcnt[blockIdx.x], 1u);
    }
    __syncthreads();
    if (s_old != NPT - 1) return;
    __threadfence();   // acquire: g_pmax column + g_qn slice are visible

    // ---- epilogue A: this block is last in its column -> CE for 32 queries ----
    {
        int lane = t & 31;
        int wid  = t >> 5;
        float lsum = 0.0f;

        #pragma unroll
        for (int i = 0; i < 4; i++) {
            int q = qbase + wid * 4 + i;

            float v = (lane < NPT) ? g_pmax[q * NPT + lane] : -3e38f;
            #pragma unroll
            for (int o = 16; o; o >>= 1) v = fmaxf(v, __shfl_xor_sync(0xffffffffu, v, o));
            float l0 = v * TAUI;

            float4 qv = *(const float4*)(g_qn + (size_t)q * CC + lane * 4);

            float ln[NNEG];
            #pragma unroll
            for (int n = 0; n < NNEG; n++) {
                float4 nv = *(const float4*)(neg + ((size_t)q * NNEG + n) * CC + lane * 4);
                float dp = qv.x * nv.x + qv.y * nv.y + qv.z * nv.z + qv.w * nv.w;
                float ss = nv.x * nv.x + nv.y * nv.y + nv.z * nv.z + nv.w * nv.w;
                #pragma unroll
                for (int o = 16; o; o >>= 1) {
                    dp += __shfl_xor_sync(0xffffffffu, dp, o);
                    ss += __shfl_xor_sync(0xffffffffu, ss, o);
                }
                ln[n] = dp / fmaxf(sqrtf(ss), 1e-12f) * TAUI;
            }

            float m = l0;
            #pragma unroll
            for (int n = 0; n < NNEG; n++) m = fmaxf(m, ln[n]);
            float se = expf(l0 - m);
            #pragma unroll
            for (int n = 0; n < NNEG; n++) se += expf(ln[n] - m);
            lsum += logf(se) + m - l0;           // = -(log_softmax[0])
        }

        if (lane == 0) s_loss[wid] = lsum;
    }
    __syncthreads();

    if (t == 0) {
        float colsum = 0.0f;
        #pragma unroll
        for (int i = 0; i < 8; i++) colsum += s_loss[i];
        g_partial[blockIdx.x] = colsum;
        g_colcnt[blockIdx.x] = 0;                // reset for next replay
        __threadfence();
        unsigned int old2 = atomicAdd(&g_done, 1u);
        if (old2 == 15u) {
            __threadfence();                     // acquire all g_partial
            float tot = 0.0f;
            #pragma unroll
            for (int i = 0; i < 16; i++) tot += g_partial[i];
            out[0] = tot * (1.0f / (float)BK);
            g_done = 0u;                         // reset for next replay
        }
    }
}

// ---------------------------------------------------------------------------
extern "C" void kernel_launch(void* const* d_in, const int* in_sizes, int n_in,
                              void* d_out, int out_size) {
    const float* qf   = (const float*)d_in[0];  // [8,128,512,512]
    const float* pool = (const float*)d_in[1];  // [4096,128]
    const float* neg  = (const float*)d_in[2];  // [8,64,7,128]
    const int*   qidx = (const int*)d_in[3];    // [8,64]
    float* out = (float*)d_out;

    const int smem = (CC * QT + CC * PSTR) * (int)sizeof(float); // 83968 B
    cudaFuncSetAttribute(k_fused, cudaFuncAttributeMaxDynamicSharedMemorySize, smem);

    k_fused<<<dim3(BK / QT, PP / PTILE), 256, smem>>>(pool, qf, qidx, neg, out);
}

// round 8
// speedup vs baseline: 1.1984x; 1.1984x over previous
#include <cuda_runtime.h>
#include <math.h>

// Problem constants
#define CC    128
#define HWSZ  262144      // 512*512
#define BK    512         // B*K
#define NNEG  7
#define PP    4096
#define TAUI  (1.0f/0.07f)

// GEMM tiling
#define QT     32         // queries per block tile
#define PTILE  256        // protos per block
#define PCHUNK 128        // protos staged in smem at once
#define PSTR   132        // padded k-major stride for p tile
#define NPT    (PP/PTILE) // 16 proto tiles

// Scratch (device globals — no allocation allowed)
__device__ float g_qn[BK*CC];      // normalized query vectors
__device__ float g_pmax[BK*NPT];   // per (query, ptile) max similarity

// ---- packed fp32x2 helpers (sm_100+) --------------------------------------
__device__ __forceinline__ void ffma2(unsigned long long& acc,
                                      unsigned long long a, unsigned long long b) {
    asm("fma.rn.f32x2 %0, %1, %2, %0;" : "+l"(acc) : "l"(a), "l"(b));
}
__device__ __forceinline__ unsigned long long dup2(float x) {
    unsigned long long r;
    asm("mov.b64 %0, {%1, %1};" : "=l"(r) : "f"(x));
    return r;
}
__device__ __forceinline__ float2 unpack2(unsigned long long v) {
    float2 r;
    asm("mov.b64 {%0, %1}, %2;" : "=f"(r.x), "=f"(r.y) : "l"(v));
    return r;
}

// ---------------------------------------------------------------------------
// Kernel A: fused sim GEMM.  grid=(16,16), block=256
//   Gather+normalize 32 queries from qf (by==0 blocks publish g_qn), stage
//   proto chunks k-major (norms computed during staging), 8q x 2p FFMA2
//   microtile, per-(q, ptile) running max -> g_pmax.
// ---------------------------------------------------------------------------
__global__ void __launch_bounds__(256, 2)
k_gemm(const float* __restrict__ pool,
       const float* __restrict__ qf,
       const int*   __restrict__ qidx,
       float* __restrict__ out) {
    extern __shared__ float sm[];
    float* q_t = sm;            // [128][QT]   k-major
    float* p_t = sm + CC * QT;  // [128][PSTR] k-major, padded
    __shared__ float psum[2 * PCHUNK];      // proto half sums of squares
    __shared__ float qpart[8 * QT];         // gather partial sums [seg][q]

    int t     = threadIdx.x;
    int qbase = blockIdx.x * QT;
    int pbase = blockIdx.y * PTILE;

    if (blockIdx.x == 0 && blockIdx.y == 0 && t == 0) out[0] = 0.0f;

    // ---- issue the query gather loads first (16 independent LDG, MLP=16) ----
    int gq = t & 31, seg = t >> 5;                 // q within tile, c-segment
    int gidx = qidx[qbase + gq];
    int gb   = (qbase + gq) >> 6;
    const float* gsrc = qf + ((size_t)(gb * CC + seg * 16)) * HWSZ + (size_t)gidx;
    float gv[16];
    #pragma unroll
    for (int i = 0; i < 16; i++) gv[i] = gsrc[(size_t)i * HWSZ];

    // ---- stage proto chunk 0 (transposed) + per-half sumsq ----
    int sp = t & 127, half = t >> 7;
    {
        const float* src = pool + (size_t)(pbase + sp) * CC + half * 64;
        float ssp = 0.0f;
        #pragma unroll
        for (int i = 0; i < 16; i++) {
            float4 v = *(const float4*)(src + i * 4);
            ssp += v.x * v.x + v.y * v.y + v.z * v.z + v.w * v.w;
            int k0 = half * 64 + i * 4;
            p_t[(k0 + 0) * PSTR + sp] = v.x;
            p_t[(k0 + 1) * PSTR + sp] = v.y;
            p_t[(k0 + 2) * PSTR + sp] = v.z;
            p_t[(k0 + 3) * PSTR + sp] = v.w;
        }
        psum[half * PCHUNK + sp] = ssp;
    }

    // ---- finish query gather: partial sumsq -> reduce -> normalized store ----
    {
        float ss = 0.0f;
        #pragma unroll
        for (int i = 0; i < 16; i++) ss += gv[i] * gv[i];
        qpart[seg * QT + gq] = ss;
    }
    __syncthreads();
    {
        float tot = 0.0f;
        #pragma unroll
        for (int s = 0; s < 8; s++) tot += qpart[s * QT + gq];
        float inv = 1.0f / fmaxf(sqrtf(tot), 1e-12f);
        #pragma unroll
        for (int i = 0; i < 16; i++) {
            float nv = gv[i] * inv;
            q_t[(seg * 16 + i) * QT + gq] = nv;   // lanes vary q: no conflicts
            if (blockIdx.y == 0) g_qn[(qbase + gq) * CC + seg * 16 + i] = nv;
        }
    }

    int qrow = t >> 6;   // 0..3  -> queries 8*qrow .. +7
    int pcol = t & 63;   // 0..63 -> protos  2*pcol, 2*pcol+1 (within chunk)

    float bv[8];
    #pragma unroll
    for (int i = 0; i < 8; i++) bv[i] = -3e38f;

    #pragma unroll
    for (int c = 0; c < PTILE / PCHUNK; c++) {
        if (c > 0) {
            __syncthreads();   // previous chunk fully consumed
            const float* src = pool + (size_t)(pbase + c * PCHUNK + sp) * CC + half * 64;
            float ssp = 0.0f;
            #pragma unroll
            for (int i = 0; i < 16; i++) {
                float4 v = *(const float4*)(src + i * 4);
                ssp += v.x * v.x + v.y * v.y + v.z * v.z + v.w * v.w;
                int k0 = half * 64 + i * 4;
                p_t[(k0 + 0) * PSTR + sp] = v.x;
                p_t[(k0 + 1) * PSTR + sp] = v.y;
                p_t[(k0 + 2) * PSTR + sp] = v.z;
                p_t[(k0 + 3) * PSTR + sp] = v.w;
            }
            psum[half * PCHUNK + sp] = ssp;
        }
        __syncthreads();

        unsigned long long acc[4][2];
        #pragma unroll
        for (int i = 0; i < 4; i++) { acc[i][0] = 0ull; acc[i][1] = 0ull; }

        const float* qp = q_t + 8 * qrow;
        const float* pp = p_t + 2 * pcol;
        #pragma unroll 8
        for (int k = 0; k < CC; k++) {
            ulonglong2 qa = *(const ulonglong2*)(qp + k * QT);      // broadcast
            ulonglong2 qb = *(const ulonglong2*)(qp + k * QT + 4);  // broadcast
            float2 pv = *(const float2*)(pp + k * PSTR);
            unsigned long long d0 = dup2(pv.x);
            unsigned long long d1 = dup2(pv.y);
            ffma2(acc[0][0], qa.x, d0); ffma2(acc[0][1], qa.x, d1);
            ffma2(acc[1][0], qa.y, d0); ffma2(acc[1][1], qa.y, d1);
            ffma2(acc[2][0], qb.x, d0); ffma2(acc[2][1], qb.x, d1);
            ffma2(acc[3][0], qb.y, d0); ffma2(acc[3][1], qb.y, d1);
        }

        // proto reciprocal norms from staged sums of squares
        float r0 = 1.0f / fmaxf(sqrtf(psum[2*pcol]   + psum[PCHUNK + 2*pcol]),   1e-12f);
        float r1 = 1.0f / fmaxf(sqrtf(psum[2*pcol+1] + psum[PCHUNK + 2*pcol+1]), 1e-12f);
        #pragma unroll
        for (int i = 0; i < 4; i++) {
            float2 a0 = unpack2(acc[i][0]);
            float2 a1 = unpack2(acc[i][1]);
            bv[2*i]   = fmaxf(bv[2*i],   fmaxf(a0.x * r0, a1.x * r1));
            bv[2*i+1] = fmaxf(bv[2*i+1], fmaxf(a0.y * r0, a1.y * r1));
        }
    }

    // max across the 32 lanes of each warp (warp shares qrow)
    #pragma unroll
    for (int o = 16; o; o >>= 1)
        #pragma unroll
        for (int i = 0; i < 8; i++)
            bv[i] = fmaxf(bv[i], __shfl_down_sync(0xffffffffu, bv[i], o));

    // combine the two warps sharing each qrow via smem, publish g_pmax
    __syncthreads();
    int w = t >> 5;
    if ((t & 31) == 0) {
        #pragma unroll
        for (int i = 0; i < 8; i++) q_t[w * 8 + i] = bv[i];
    }
    __syncthreads();
    if (t < 32) {
        int r = t >> 3, qi = t & 7;
        float m = fmaxf(q_t[(2*r) * 8 + qi], q_t[(2*r+1) * 8 + qi]);
        g_pmax[(qbase + 8*r + qi) * NPT + blockIdx.y] = m;
    }
}

// ---------------------------------------------------------------------------
// Kernel B: negatives + softmax CE + mean.  grid=128, block=256
//   4 queries per block, 2 warps per query:
//     role 0: negs 0..3     role 1: negs 4..6 + positive logit from g_pmax
// ---------------------------------------------------------------------------
__global__ void k_final(const float* __restrict__ neg, float* __restrict__ out) {
    __shared__ float slog[4][8];    // [query][logit slot]  slot0 = positive
    __shared__ float s_loss[4];

    int t    = threadIdx.x;
    int wid  = t >> 5;              // 0..7
    int lane = t & 31;
    int qi   = wid >> 1;            // 0..3  query within block
    int role = wid & 1;
    int q    = blockIdx.x * 4 + qi;

    float4 qv = *(const float4*)(g_qn + (size_t)q * CC + lane * 4);

    int nbeg = role ? 4 : 0;
    int ncnt = role ? 3 : 4;

    float ln[4];
    #pragma unroll
    for (int n = 0; n < 4; n++) {
        if (n < ncnt) {
            float4 nv = *(const float4*)(neg + ((size_t)q * NNEG + nbeg + n) * CC + lane * 4);
            float dp = qv.x * nv.x + qv.y * nv.y + qv.z * nv.z + qv.w * nv.w;
            float ss = nv.x * nv.x + nv.y * nv.y + nv.z * nv.z + nv.w * nv.w;
            #pragma unroll
            for (int o = 16; o; o >>= 1) {
                dp += __shfl_xor_sync(0xffffffffu, dp, o);
                ss += __shfl_xor_sync(0xffffffffu, ss, o);
            }
            ln[n] = dp / fmaxf(sqrtf(ss), 1e-12f) * TAUI;
        }
    }

    float l0 = 0.0f;
    if (role) {
        float v = (lane < NPT) ? g_pmax[q * NPT + lane] : -3e38f;
        #pragma unroll
        for (int o = 16; o; o >>= 1) v = fmaxf(v, __shfl_xor_sync(0xffffffffu, v, o));
        l0 = v * TAUI;
    }

    if (lane == 0) {
        #pragma unroll
        for (int n = 0; n < 4; n++)
            if (n < ncnt) slog[qi][1 + nbeg + n] = ln[n];
        if (role) slog[qi][0] = l0;
    }
    __syncthreads();

    if (t < 4) {
        float m = slog[t][0];
        #pragma unroll
        for (int j = 1; j < 8; j++) m = fmaxf(m, slog[t][j]);
        float se = 0.0f;
        #pragma unroll
        for (int j = 0; j < 8; j++) se += expf(slog[t][j] - m);
        s_loss[t] = logf(se) + m - slog[t][0];   // = -(log_softmax[0])
    }
    __syncthreads();
    if (t == 0) {
        float bl = s_loss[0] + s_loss[1] + s_loss[2] + s_loss[3];
        atomicAdd(out, bl * (1.0f / (float)BK));
    }
}

// ---------------------------------------------------------------------------
extern "C" void kernel_launch(void* const* d_in, const int* in_sizes, int n_in,
                              void* d_out, int out_size) {
    const float* qf   = (const float*)d_in[0];  // [8,128,512,512]
    const float* pool = (const float*)d_in[1];  // [4096,128]
    const float* neg  = (const float*)d_in[2];  // [8,64,7,128]
    const int*   qidx = (const int*)d_in[3];    // [8,64]
    float* out = (float*)d_out;

    const int smem = (CC * QT + CC * PSTR) * (int)sizeof(float); // 83968 B
    cudaFuncSetAttribute(k_gemm, cudaFuncAttributeMaxDynamicSharedMemorySize, smem);

    k_gemm<<<dim3(BK / QT, PP / PTILE), 256, smem>>>(pool, qf, qidx, out);
    k_final<<<BK / 4, 256>>>(neg, out);
}

// round 9
// speedup vs baseline: 1.3363x; 1.1151x over previous
#include <cuda_runtime.h>
#include <math.h>

// Problem constants
#define CC    128
#define HWSZ  262144      // 512*512
#define BK    512         // B*K
#define NNEG  7
#define PP    4096
#define TAUI  (1.0f/0.07f)

// GEMM tiling
#define QT     32         // queries per block tile
#define PTILE  256        // protos per block
#define PCHUNK 128        // protos staged in smem at once
#define PSTR   132        // padded k-major stride for p tile
#define NPT    (PP/PTILE) // 16 proto tiles

// Scratch (device globals — no allocation allowed)
__device__ float g_qn[BK*CC];      // normalized query vectors
__device__ float g_pmax[BK*NPT];   // per (query, ptile) max similarity

// ---- packed fp32x2 helpers (sm_100+) --------------------------------------
__device__ __forceinline__ void ffma2(unsigned long long& acc,
                                      unsigned long long a, unsigned long long b) {
    asm("fma.rn.f32x2 %0, %1, %2, %0;" : "+l"(acc) : "l"(a), "l"(b));
}
__device__ __forceinline__ unsigned long long dup2(float x) {
    unsigned long long r;
    asm("mov.b64 %0, {%1, %1};" : "=l"(r) : "f"(x));
    return r;
}
__device__ __forceinline__ float2 unpack2(unsigned long long v) {
    float2 r;
    asm("mov.b64 {%0, %1}, %2;" : "=f"(r.x), "=f"(r.y) : "l"(v));
    return r;
}

// ---------------------------------------------------------------------------
// Kernel A: query gather + L2 normalize ONLY.  grid=256, block=256
//   2 queries per block (128 threads each); one scattered load per thread.
//   Thread 0 of block 0 zeroes the output accumulator.
// ---------------------------------------------------------------------------
__global__ void k_prep(const float* __restrict__ qf,
                       const int*   __restrict__ qidx,
                       float* __restrict__ out) {
    __shared__ float sred[8];
    int t   = threadIdx.x;
    int grp = t >> 7;                       // 0 or 1
    int q   = blockIdx.x * 2 + grp;
    int c   = t & 127;

    if (blockIdx.x == 0 && t == 0) out[0] = 0.0f;

    int b   = q >> 6;
    int idx = qidx[q];
    float v = qf[((size_t)(b * CC + c)) * HWSZ + (size_t)idx];
    float ss = v * v;
    #pragma unroll
    for (int o = 16; o; o >>= 1) ss += __shfl_xor_sync(0xffffffffu, ss, o);
    if ((t & 31) == 0) sred[t >> 5] = ss;
    __syncthreads();
    float tot = sred[grp * 4 + 0] + sred[grp * 4 + 1]
              + sred[grp * 4 + 2] + sred[grp * 4 + 3];
    float inv = 1.0f / fmaxf(sqrtf(tot), 1e-12f);
    g_qn[q * CC + c] = v * inv;
}

// ---------------------------------------------------------------------------
// Kernel B: sim GEMM.  grid=(16,16), block=256
//   Loads q tile from g_qn (contiguous), stages proto chunks k-major with
//   norms computed during staging, 8q x 2p FFMA2 microtile, running max.
// ---------------------------------------------------------------------------
__global__ void __launch_bounds__(256, 2)
k_gemm(const float* __restrict__ pool) {
    extern __shared__ float sm[];
    float* q_t = sm;            // [128][QT]   k-major
    float* p_t = sm + CC * QT;  // [128][PSTR] k-major, padded
    __shared__ float psum[2 * PCHUNK];      // proto half sums of squares

    int t     = threadIdx.x;
    int qbase = blockIdx.x * QT;
    int pbase = blockIdx.y * PTILE;

    // ---- load q tile transposed from g_qn (lanes vary q -> conflict-free) ----
    {
        int q = t & 31, part = t >> 5;          // 8 parts x 16 k each
        const float* src = g_qn + (size_t)(qbase + q) * CC + part * 16;
        #pragma unroll
        for (int i = 0; i < 4; i++) {
            float4 v = *(const float4*)(src + i * 4);
            int k0 = part * 16 + i * 4;
            q_t[(k0 + 0) * QT + q] = v.x;
            q_t[(k0 + 1) * QT + q] = v.y;
            q_t[(k0 + 2) * QT + q] = v.z;
            q_t[(k0 + 3) * QT + q] = v.w;
        }
    }

    // ---- stage proto chunk 0 (transposed) + per-half sumsq ----
    int sp = t & 127, half = t >> 7;
    {
        const float* src = pool + (size_t)(pbase + sp) * CC + half * 64;
        float ssp = 0.0f;
        #pragma unroll
        for (int i = 0; i < 16; i++) {
            float4 v = *(const float4*)(src + i * 4);
            ssp += v.x * v.x + v.y * v.y + v.z * v.z + v.w * v.w;
            int k0 = half * 64 + i * 4;
            p_t[(k0 + 0) * PSTR + sp] = v.x;
            p_t[(k0 + 1) * PSTR + sp] = v.y;
            p_t[(k0 + 2) * PSTR + sp] = v.z;
            p_t[(k0 + 3) * PSTR + sp] = v.w;
        }
        psum[half * PCHUNK + sp] = ssp;
    }

    int qrow = t >> 6;   // 0..3  -> queries 8*qrow .. +7
    int pcol = t & 63;   // 0..63 -> protos  2*pcol, 2*pcol+1 (within chunk)

    float bv[8];
    #pragma unroll
    for (int i = 0; i < 8; i++) bv[i] = -3e38f;

    #pragma unroll
    for (int c = 0; c < PTILE / PCHUNK; c++) {
        if (c > 0) {
            __syncthreads();   // previous chunk fully consumed
            const float* src = pool + (size_t)(pbase + c * PCHUNK + sp) * CC + half * 64;
            float ssp = 0.0f;
            #pragma unroll
            for (int i = 0; i < 16; i++) {
                float4 v = *(const float4*)(src + i * 4);
                ssp += v.x * v.x + v.y * v.y + v.z * v.z + v.w * v.w;
                int k0 = half * 64 + i * 4;
                p_t[(k0 + 0) * PSTR + sp] = v.x;
                p_t[(k0 + 1) * PSTR + sp] = v.y;
                p_t[(k0 + 2) * PSTR + sp] = v.z;
                p_t[(k0 + 3) * PSTR + sp] = v.w;
            }
            psum[half * PCHUNK + sp] = ssp;
        }
        __syncthreads();

        unsigned long long acc[4][2];
        #pragma unroll
        for (int i = 0; i < 4; i++) { acc[i][0] = 0ull; acc[i][1] = 0ull; }

        const float* qp = q_t + 8 * qrow;
        const float* pp = p_t + 2 * pcol;
        #pragma unroll 8
        for (int k = 0; k < CC; k++) {
            ulonglong2 qa = *(const ulonglong2*)(qp + k * QT);      // broadcast
            ulonglong2 qb = *(const ulonglong2*)(qp + k * QT + 4);  // broadcast
            float2 pv = *(const float2*)(pp + k * PSTR);
            unsigned long long d0 = dup2(pv.x);
            unsigned long long d1 = dup2(pv.y);
            ffma2(acc[0][0], qa.x, d0); ffma2(acc[0][1], qa.x, d1);
            ffma2(acc[1][0], qa.y, d0); ffma2(acc[1][1], qa.y, d1);
            ffma2(acc[2][0], qb.x, d0); ffma2(acc[2][1], qb.x, d1);
            ffma2(acc[3][0], qb.y, d0); ffma2(acc[3][1], qb.y, d1);
        }

        // proto reciprocal norms from staged sums of squares
        float r0 = 1.0f / fmaxf(sqrtf(psum[2*pcol]   + psum[PCHUNK + 2*pcol]),   1e-12f);
        float r1 = 1.0f / fmaxf(sqrtf(psum[2*pcol+1] + psum[PCHUNK + 2*pcol+1]), 1e-12f);
        #pragma unroll
        for (int i = 0; i < 4; i++) {
            float2 a0 = unpack2(acc[i][0]);
            float2 a1 = unpack2(acc[i][1]);
            bv[2*i]   = fmaxf(bv[2*i],   fmaxf(a0.x * r0, a1.x * r1));
            bv[2*i+1] = fmaxf(bv[2*i+1], fmaxf(a0.y * r0, a1.y * r1));
        }
    }

    // max across the 32 lanes of each warp (warp shares qrow)
    #pragma unroll
    for (int o = 16; o; o >>= 1)
        #pragma unroll
        for (int i = 0; i < 8; i++)
            bv[i] = fmaxf(bv[i], __shfl_down_sync(0xffffffffu, bv[i], o));

    // combine the two warps sharing each qrow via smem, publish g_pmax
    __syncthreads();
    int w = t >> 5;
    if ((t & 31) == 0) {
        #pragma unroll
        for (int i = 0; i < 8; i++) q_t[w * 8 + i] = bv[i];
    }
    __syncthreads();
    if (t < 32) {
        int r = t >> 3, qi = t & 7;
        float m = fmaxf(q_t[(2*r) * 8 + qi], q_t[(2*r+1) * 8 + qi]);
        g_pmax[(qbase + 8*r + qi) * NPT + blockIdx.y] = m;
    }
}

// ---------------------------------------------------------------------------
// Kernel C: negatives + softmax CE + mean.  grid=128, block=256
//   4 queries per block, 2 warps per query:
//     role 0: negs 0..3     role 1: negs 4..6 + positive logit from g_pmax
// ---------------------------------------------------------------------------
__global__ void k_final(const float* __restrict__ neg, float* __restrict__ out) {
    __shared__ float slog[4][8];    // [query][logit slot]  slot0 = positive
    __shared__ float s_loss[4];

    int t    = threadIdx.x;
    int wid  = t >> 5;              // 0..7
    int lane = t & 31;
    int qi   = wid >> 1;            // 0..3  query within block
    int role = wid & 1;
    int q    = blockIdx.x * 4 + qi;

    float4 qv = *(const float4*)(g_qn + (size_t)q * CC + lane * 4);

    int nbeg = role ? 4 : 0;
    int ncnt = role ? 3 : 4;

    float ln[4];
    #pragma unroll
    for (int n = 0; n < 4; n++) {
        if (n < ncnt) {
            float4 nv = *(const float4*)(neg + ((size_t)q * NNEG + nbeg + n) * CC + lane * 4);
            float dp = qv.x * nv.x + qv.y * nv.y + qv.z * nv.z + qv.w * nv.w;
            float ss = nv.x * nv.x + nv.y * nv.y + nv.z * nv.z + nv.w * nv.w;
            #pragma unroll
            for (int o = 16; o; o >>= 1) {
                dp += __shfl_xor_sync(0xffffffffu, dp, o);
                ss += __shfl_xor_sync(0xffffffffu, ss, o);
            }
            ln[n] = dp / fmaxf(sqrtf(ss), 1e-12f) * TAUI;
        }
    }

    float l0 = 0.0f;
    if (role) {
        float v = (lane < NPT) ? g_pmax[q * NPT + lane] : -3e38f;
        #pragma unroll
        for (int o = 16; o; o >>= 1) v = fmaxf(v, __shfl_xor_sync(0xffffffffu, v, o));
        l0 = v * TAUI;
    }

    if (lane == 0) {
        #pragma unroll
        for (int n = 0; n < 4; n++)
            if (n < ncnt) slog[qi][1 + nbeg + n] = ln[n];
        if (role) slog[qi][0] = l0;
    }
    __syncthreads();

    if (t < 4) {
        float m = slog[t][0];
        #pragma unroll
        for (int j = 1; j < 8; j++) m = fmaxf(m, slog[t][j]);
        float se = 0.0f;
        #pragma unroll
        for (int j = 0; j < 8; j++) se += expf(slog[t][j] - m);
        s_loss[t] = logf(se) + m - slog[t][0];   // = -(log_softmax[0])
    }
    __syncthreads();
    if (t == 0) {
        float bl = s_loss[0] + s_loss[1] + s_loss[2] + s_loss[3];
        atomicAdd(out, bl * (1.0f / (float)BK));
    }
}

// ---------------------------------------------------------------------------
extern "C" void kernel_launch(void* const* d_in, const int* in_sizes, int n_in,
                              void* d_out, int out_size) {
    const float* qf   = (const float*)d_in[0];  // [8,128,512,512]
    const float* pool = (const float*)d_in[1];  // [4096,128]
    const float* neg  = (const float*)d_in[2];  // [8,64,7,128]
    const int*   qidx = (const int*)d_in[3];    // [8,64]
    float* out = (float*)d_out;

    const int smem = (CC * QT + CC * PSTR) * (int)sizeof(float); // 83968 B
    cudaFuncSetAttribute(k_gemm, cudaFuncAttributeMaxDynamicSharedMemorySize, smem);

    k_prep<<<BK / 2, 256>>>(qf, qidx, out);
    k_gemm<<<dim3(BK / QT, PP / PTILE), 256, smem>>>(pool);
    k_final<<<BK / 4, 256>>>(neg, out);
}

// round 12
// speedup vs baseline: 2.5101x; 1.8784x over previous
#include <cuda_runtime.h>
#include <cuda_bf16.h>
#include <math.h>
#include <stdint.h>

// Problem constants
#define CC    128
#define HWSZ  262144      // 512*512
#define BK    512         // B*K
#define NNEG  7
#define PP    4096
#define TAUI  (1.0f/0.07f)

// MMA tiling
#define QTILE 128
#define PTILE 128
#define NPT   (PP/PTILE)  // 32 proto tiles

// smem layout for k_mma: 4 tiles of 128 rows x 272 B (256 data + 16 pad)
#define STRB    272
#define TILE_B  (128*STRB)    // 34816
#define AH_OFF  0
#define AL_OFF  (TILE_B)
#define BH_OFF  (2*TILE_B)
#define BL_OFF  (3*TILE_B)
#define RN_OFF  (4*TILE_B)    // 139264
#define SMEM_MMA (RN_OFF + 512)

// Scratch (device globals — no allocation allowed)
__device__ __align__(256) float         g_qn[BK*CC];
__device__ __align__(256) float         g_rnorm[PP];
__device__ __align__(256) float         g_pmax[BK*NPT];
__device__ __align__(256) __nv_bfloat16 g_qh[BK*CC];
__device__ __align__(256) __nv_bfloat16 g_ql[BK*CC];
__device__ __align__(256) __nv_bfloat16 g_ph[PP*CC];
__device__ __align__(256) __nv_bfloat16 g_pl[PP*CC];

__device__ __forceinline__ uint32_t smem_u32(const void* p) {
    uint32_t a;
    asm("{ .reg .u64 t; cvta.to.shared.u64 t, %1; cvt.u32.u64 %0, t; }"
        : "=r"(a) : "l"(p));
    return a;
}

#define LDSM4(r0, r1, r2, r3, addr) \
    asm volatile("ldmatrix.sync.aligned.m8n8.x4.shared.b16 {%0,%1,%2,%3}, [%4];" \
        : "=r"(r0), "=r"(r1), "=r"(r2), "=r"(r3) : "r"(addr))

#define MMA16816(c, a0, a1, a2, a3, b0, b1) \
    asm volatile("mma.sync.aligned.m16n8k16.row.col.f32.bf16.bf16.f32 " \
        "{%0,%1,%2,%3}, {%4,%5,%6,%7}, {%8,%9}, {%0,%1,%2,%3};" \
        : "+f"((c)[0]), "+f"((c)[1]), "+f"((c)[2]), "+f"((c)[3]) \
        : "r"(a0), "r"(a1), "r"(a2), "r"(a3), "r"(b0), "r"(b1))

// ---------------------------------------------------------------------------
// Kernel 1: prep.  grid=768, block=256
//   blocks [0,512): pool rows (8/block, warp per row): rnorm + bf16 hi/lo split
//   blocks [512,768): queries (2/block): gather, normalize, g_qn + bf16 split
// ---------------------------------------------------------------------------
__global__ void k_prep(const float* __restrict__ pool,
                       const float* __restrict__ qf,
                       const int*   __restrict__ qidx,
                       float* __restrict__ out) {
    int bid = blockIdx.x;
    int t   = threadIdx.x;
    if (bid == 0 && t == 0) out[0] = 0.0f;

    if (bid < 512) {
        int p    = bid * 8 + (t >> 5);
        int lane = t & 31;
        float4 v = *(const float4*)(pool + (size_t)p * CC + lane * 4);
        float ss = v.x*v.x + v.y*v.y + v.z*v.z + v.w*v.w;
        #pragma unroll
        for (int o = 16; o; o >>= 1) ss += __shfl_xor_sync(0xffffffffu, ss, o);
        if (lane == 0) g_rnorm[p] = 1.0f / fmaxf(sqrtf(ss), 1e-12f);

        float vv[4] = {v.x, v.y, v.z, v.w};
        uint32_t hp[2], lp[2];
        #pragma unroll
        for (int i = 0; i < 2; i++) {
            __nv_bfloat16 h0 = __float2bfloat16(vv[2*i]);
            __nv_bfloat16 h1 = __float2bfloat16(vv[2*i+1]);
            __nv_bfloat16 l0 = __float2bfloat16(vv[2*i]   - __bfloat162float(h0));
            __nv_bfloat16 l1 = __float2bfloat16(vv[2*i+1] - __bfloat162float(h1));
            hp[i] = (uint32_t)__bfloat16_as_ushort(h0)
                  | ((uint32_t)__bfloat16_as_ushort(h1) << 16);
            lp[i] = (uint32_t)__bfloat16_as_ushort(l0)
                  | ((uint32_t)__bfloat16_as_ushort(l1) << 16);
        }
        *(uint2*)((char*)g_ph + ((size_t)p * CC + lane * 4) * 2) = make_uint2(hp[0], hp[1]);
        *(uint2*)((char*)g_pl + ((size_t)p * CC + lane * 4) * 2) = make_uint2(lp[0], lp[1]);
    } else {
        __shared__ float sred[8];
        int grp = t >> 7;
        int q   = (bid - 512) * 2 + grp;
        int c   = t & 127;
        int b   = q >> 6;
        int idx = qidx[q];
        float v = qf[((size_t)(b * CC + c)) * HWSZ + (size_t)idx];
        float ss = v * v;
        #pragma unroll
        for (int o = 16; o; o >>= 1) ss += __shfl_xor_sync(0xffffffffu, ss, o);
        if ((t & 31) == 0) sred[t >> 5] = ss;
        __syncthreads();
        float tot = sred[grp*4+0] + sred[grp*4+1] + sred[grp*4+2] + sred[grp*4+3];
        float inv = 1.0f / fmaxf(sqrtf(tot), 1e-12f);
        float nv = v * inv;
        g_qn[q * CC + c] = nv;
        __nv_bfloat16 h = __float2bfloat16(nv);
        g_qh[q * CC + c] = h;
        g_ql[q * CC + c] = __float2bfloat16(nv - __bfloat162float(h));
    }
}

// ---------------------------------------------------------------------------
// Kernel 2: split-bf16 tensor GEMM via mma.sync.  grid=(4,32), block=256
//   D = Ah*Bh + Ah*Bl + Al*Bh (fp32 accum); sim = D * rnorm; row max -> g_pmax
//   warp w: m-rows 16w..16w+15, all 128 protos.  A,B frags via ldmatrix.x4.
// ---------------------------------------------------------------------------
__global__ void __launch_bounds__(256, 1) k_mma() {
    extern __shared__ __align__(128) uint8_t smem[];
    int t    = threadIdx.x;
    int lane = t & 31;
    int wid  = t >> 5;
    int qbase = blockIdx.x * QTILE;
    int pbase = blockIdx.y * PTILE;

    // ---- stage 4 tiles (row-major, 272B stride) + rnorm ----
    {
        int row = t >> 1, half = t & 1;
        const uint4* sah = (const uint4*)((const char*)(g_qh + (size_t)(qbase + row) * CC) + half * 128);
        const uint4* sal = (const uint4*)((const char*)(g_ql + (size_t)(qbase + row) * CC) + half * 128);
        const uint4* sbh = (const uint4*)((const char*)(g_ph + (size_t)(pbase + row) * CC) + half * 128);
        const uint4* sbl = (const uint4*)((const char*)(g_pl + (size_t)(pbase + row) * CC) + half * 128);
        uint4* dah = (uint4*)(smem + AH_OFF + row * STRB + half * 128);
        uint4* dal = (uint4*)(smem + AL_OFF + row * STRB + half * 128);
        uint4* dbh = (uint4*)(smem + BH_OFF + row * STRB + half * 128);
        uint4* dbl = (uint4*)(smem + BL_OFF + row * STRB + half * 128);
        #pragma unroll
        for (int i = 0; i < 8; i++) {
            dah[i] = sah[i]; dal[i] = sal[i];
            dbh[i] = sbh[i]; dbl[i] = sbl[i];
        }
        if (t < 128) ((float*)(smem + RN_OFF))[t] = g_rnorm[pbase + t];
    }
    __syncthreads();

    uint32_t sb = smem_u32(smem);
    int m0 = wid * 16;
    // ldmatrix lane addressing (derived from PTX fragment layouts, non-trans):
    //   A: row = m0 + (lane&15), col8 = (lane&16)?8:0
    //   B: row = (lane&7) + ((lane&16)?8:0), col8 = (lane&8)?8:0
    uint32_t aoff = (uint32_t)((m0 + (lane & 15)) * STRB + ((lane & 16) ? 16 : 0));
    uint32_t boff = (uint32_t)(((lane & 7) + ((lane & 16) ? 8 : 0)) * STRB + ((lane & 8) ? 16 : 0));
    uint32_t aAh = sb + AH_OFF + aoff;
    uint32_t aAl = sb + AL_OFF + aoff;
    uint32_t bBh = sb + BH_OFF + boff;
    uint32_t bBl = sb + BL_OFF + boff;

    float acc[16][4];
    #pragma unroll
    for (int i = 0; i < 16; i++)
        #pragma unroll
        for (int j = 0; j < 4; j++) acc[i][j] = 0.0f;

    for (int ks = 0; ks < 8; ks++) {
        uint32_t kb = ks * 32;   // 16 bf16 = 32 bytes
        uint32_t ah0, ah1, ah2, ah3, al0, al1, al2, al3;
        LDSM4(ah0, ah1, ah2, ah3, aAh + kb);
        LDSM4(al0, al1, al2, al3, aAl + kb);
        #pragma unroll
        for (int j = 0; j < 8; j++) {
            uint32_t bh0, bh1, bh2, bh3, bl0, bl1, bl2, bl3;
            LDSM4(bh0, bh1, bh2, bh3, bBh + j * 16 * STRB + kb);
            LDSM4(bl0, bl1, bl2, bl3, bBl + j * 16 * STRB + kb);
            MMA16816(acc[2*j],   ah0, ah1, ah2, ah3, bh0, bh1);
            MMA16816(acc[2*j],   ah0, ah1, ah2, ah3, bl0, bl1);
            MMA16816(acc[2*j],   al0, al1, al2, al3, bh0, bh1);
            MMA16816(acc[2*j+1], ah0, ah1, ah2, ah3, bh2, bh3);
            MMA16816(acc[2*j+1], ah0, ah1, ah2, ah3, bl2, bl3);
            MMA16816(acc[2*j+1], al0, al1, al2, al3, bh2, bh3);
        }
    }

    // ---- epilogue: sim = acc * rnorm, max over all 128 protos ----
    const float* rn = (const float*)(smem + RN_OFF);
    float mx1 = -3e38f, mx2 = -3e38f;
    #pragma unroll
    for (int nb = 0; nb < 16; nb++) {
        int n = nb * 8 + 2 * (lane & 3);
        float r0 = rn[n], r1 = rn[n + 1];
        mx1 = fmaxf(mx1, fmaxf(acc[nb][0] * r0, acc[nb][1] * r1));
        mx2 = fmaxf(mx2, fmaxf(acc[nb][2] * r0, acc[nb][3] * r1));
    }
    #pragma unroll
    for (int o = 1; o <= 2; o <<= 1) {
        mx1 = fmaxf(mx1, __shfl_xor_sync(0xffffffffu, mx1, o));
        mx2 = fmaxf(mx2, __shfl_xor_sync(0xffffffffu, mx2, o));
    }
    if ((lane & 3) == 0) {
        int q1 = qbase + m0 + (lane >> 2);
        g_pmax[q1 * NPT + blockIdx.y]       = mx1;
        g_pmax[(q1 + 8) * NPT + blockIdx.y] = mx2;
    }
}

// ---------------------------------------------------------------------------
// Kernel 3: negatives + softmax CE + mean.  grid=128, block=256
//   4 queries per block, 2 warps per query:
//     role 0: negs 0..3     role 1: negs 4..6 + positive logit from g_pmax
// ---------------------------------------------------------------------------
__global__ void k_final(const float* __restrict__ neg, float* __restrict__ out) {
    __shared__ float slog[4][8];    // [query][logit slot]  slot0 = positive
    __shared__ float s_loss[4];

    int t    = threadIdx.x;
    int wid  = t >> 5;
    int lane = t & 31;
    int qi   = wid >> 1;
    int role = wid & 1;
    int q    = blockIdx.x * 4 + qi;

    float4 qv = *(const float4*)(g_qn + (size_t)q * CC + lane * 4);

    int nbeg = role ? 4 : 0;
    int ncnt = role ? 3 : 4;

    float ln[4];
    #pragma unroll
    for (int n = 0; n < 4; n++) {
        if (n < ncnt) {
            float4 nv = *(const float4*)(neg + ((size_t)q * NNEG + nbeg + n) * CC + lane * 4);
            float dp = qv.x*nv.x + qv.y*nv.y + qv.z*nv.z + qv.w*nv.w;
            float ss = nv.x*nv.x + nv.y*nv.y + nv.z*nv.z + nv.w*nv.w;
            #pragma unroll
            for (int o = 16; o; o >>= 1) {
                dp += __shfl_xor_sync(0xffffffffu, dp, o);
                ss += __shfl_xor_sync(0xffffffffu, ss, o);
            }
            ln[n] = dp / fmaxf(sqrtf(ss), 1e-12f) * TAUI;
        }
    }

    float l0 = 0.0f;
    if (role) {
        float v = g_pmax[q * NPT + lane];   // NPT == 32: every lane valid
        #pragma unroll
        for (int o = 16; o; o >>= 1) v = fmaxf(v, __shfl_xor_sync(0xffffffffu, v, o));
        l0 = v * TAUI;
    }

    if (lane == 0) {
        #pragma unroll
        for (int n = 0; n < 4; n++)
            if (n < ncnt) slog[qi][1 + nbeg + n] = ln[n];
        if (role) slog[qi][0] = l0;
    }
    __syncthreads();

    if (t < 4) {
        float m = slog[t][0];
        #pragma unroll
        for (int j = 1; j < 8; j++) m = fmaxf(m, slog[t][j]);
        float se = 0.0f;
        #pragma unroll
        for (int j = 0; j < 8; j++) se += expf(slog[t][j] - m);
        s_loss[t] = logf(se) + m - slog[t][0];   // = -(log_softmax[0])
    }
    __syncthreads();
    if (t == 0) {
        float bl = s_loss[0] + s_loss[1] + s_loss[2] + s_loss[3];
        atomicAdd(out, bl * (1.0f / (float)BK));
    }
}

// ---------------------------------------------------------------------------
extern "C" void kernel_launch(void* const* d_in, const int* in_sizes, int n_in,
                              void* d_out, int out_size) {
    const float* qf   = (const float*)d_in[0];  // [8,128,512,512]
    const float* pool = (const float*)d_in[1];  // [4096,128]
    const float* neg  = (const float*)d_in[2];  // [8,64,7,128]
    const int*   qidx = (const int*)d_in[3];    // [8,64]
    float* out = (float*)d_out;

    cudaFuncSetAttribute(k_mma, cudaFuncAttributeMaxDynamicSharedMemorySize, SMEM_MMA);

    k_prep<<<768, 256>>>(pool, qf, qidx, out);
    k_mma<<<dim3(BK / QTILE, PP / PTILE), 256, SMEM_MMA>>>();
    k_final<<<BK / 4, 256>>>(neg, out);
}